// round 2
// baseline (speedup 1.0000x reference)
#include <cuda_runtime.h>
#include <math.h>

// Problem dims
#define TT 512
#define BB 256
#define FF 512
#define HH 512

// Tiling: grid = NM x NH = 4 x 32 = 128 CTAs, each owns a 64-batch x 16-hcol tile
// (=> 64 gate rows: the i/f/g/o quadruple for its 16 h columns).
#define MT 64
#define HT 16
#define NM 4
#define NH 32
#define NCTA 128
#define NTH 256
#define KC 16
#define NKC 64   // (FF+HH)/KC

// Persistent device state (allocation-free scratch)
__device__ float g_h[2][BB * HH];      // ping-pong hidden state
__device__ unsigned g_count;           // barrier arrival counter
__device__ unsigned g_gen;             // barrier generation

__device__ __forceinline__ void grid_sync(unsigned target) {
    __syncthreads();
    if (threadIdx.x == 0) {
        __threadfence();
        if (atomicAdd(&g_count, 1u) == NCTA - 1) {
            atomicExch(&g_count, 0u);
            __threadfence();
            atomicExch(&g_gen, target);
        } else {
            volatile unsigned* p = &g_gen;
            while (*p != target) { }
        }
        __threadfence();   // gpu-scope fence: also invalidates this SM's L1D
    }
    __syncthreads();
}

__device__ __forceinline__ float sigf(float v) { return 1.0f / (1.0f + expf(-v)); }

__global__ void __launch_bounds__(NTH, 2) lstm_persistent(
    const float* __restrict__ x,     // (T,B,F)
    const float* __restrict__ wih,   // (4H,F)
    const float* __restrict__ whh,   // (4H,H)
    const float* __restrict__ bih,   // (4H)
    const float* __restrict__ bhh,   // (4H)
    float* __restrict__ out)         // [B*T*H h_seq][B*H h_t][B*H c_t]
{
    // K-major (transposed) staging so both A and B fragments load as LDS.128
    __shared__ __align__(16) float As[2][KC][MT];       // 8 KB
    __shared__ __align__(16) float Bs[2][KC][MT];       // 8 KB (64 gate rows)
    __shared__ float Cs[MT][4 * HT + 1];                // 16.6 KB gate outputs

    const int tid = threadIdx.x;
    const int mi = blockIdx.x & 3;        // batch tile
    const int hi = blockIdx.x >> 2;       // h-col tile
    const int m0 = mi * MT;
    const int j0 = hi * HT;

    const unsigned base_gen = *(volatile unsigned*)&g_gen;

    // ---- init: zero h0 tile (this CTA's ownership region) ----
    for (int p = tid; p < MT * HT; p += NTH) {
        int r = p >> 4, jj = p & 15;
        g_h[0][(m0 + r) * HH + j0 + jj] = 0.0f;
    }

    // Loader indexing: thread loads one float4 per matrix per chunk.
    const int lrow = tid >> 2;            // 0..63 (A: batch row / B: gate row)
    const int lq   = (tid & 3) * 4;       // k sub-offset 0/4/8/12
    // B gather row: gate quadruple for this CTA's 16 h columns
    const int wrowB = (lrow >> 4) * HH + j0 + (lrow & 15);

    // Compute indexing: 16x16 threads, 4x4 micro-tile each
    const int ty = (tid >> 4) * 4;        // C-tile row base (batch)
    const int tx = (tid & 15) * 4;        // C-tile col base (gate row)

    // Elementwise: thread handles (r = tid>>4 + 16q, jj = tid&15), q=0..3
    const int jj = tid & 15;
    const float bias_i = bih[0 * HH + j0 + jj] + bhh[0 * HH + j0 + jj];
    const float bias_f = bih[1 * HH + j0 + jj] + bhh[1 * HH + j0 + jj];
    const float bias_g = bih[2 * HH + j0 + jj] + bhh[2 * HH + j0 + jj];
    const float bias_o = bih[3 * HH + j0 + jj] + bhh[3 * HH + j0 + jj];

    float c_reg[4] = {0.0f, 0.0f, 0.0f, 0.0f};   // cell state, register-resident

    grid_sync(base_gen + 1);

    for (int t = 0; t < TT; ++t) {
        const float* __restrict__ hrd = g_h[t & 1];
        float* __restrict__ hwr = g_h[(t + 1) & 1];
        const float* __restrict__ xt = x + (long)t * (BB * FF);

        float acc[4][4];
        #pragma unroll
        for (int i = 0; i < 4; ++i)
            #pragma unroll
            for (int j = 0; j < 4; ++j) acc[i][j] = 0.0f;

        // ---- prologue: chunk 0 (x / wih region) ----
        float4 av = *(const float4*)(xt + (m0 + lrow) * FF + lq);
        float4 bv = *(const float4*)(wih + wrowB * FF + lq);
        As[0][lq + 0][lrow] = av.x; As[0][lq + 1][lrow] = av.y;
        As[0][lq + 2][lrow] = av.z; As[0][lq + 3][lrow] = av.w;
        Bs[0][lq + 0][lrow] = bv.x; Bs[0][lq + 1][lrow] = bv.y;
        Bs[0][lq + 2][lrow] = bv.z; Bs[0][lq + 3][lrow] = bv.w;
        __syncthreads();

        #pragma unroll 2
        for (int kc = 0; kc < NKC; ++kc) {
            const int cur = kc & 1;
            const bool more = (kc + 1 < NKC);
            if (more) {
                const int k0 = (kc + 1) * KC;
                if (k0 < FF) {
                    av = *(const float4*)(xt + (m0 + lrow) * FF + k0 + lq);
                    bv = *(const float4*)(wih + wrowB * FF + k0 + lq);
                } else {
                    // h from L2 (written by other CTAs last step; barrier-ordered)
                    av = __ldcg((const float4*)(hrd + (m0 + lrow) * HH + (k0 - FF) + lq));
                    bv = *(const float4*)(whh + wrowB * HH + (k0 - FF) + lq);
                }
            }
            #pragma unroll
            for (int k = 0; k < KC; ++k) {
                const float4 a = *(const float4*)&As[cur][k][ty];
                const float4 b = *(const float4*)&Bs[cur][k][tx];
                acc[0][0] += a.x * b.x; acc[0][1] += a.x * b.y; acc[0][2] += a.x * b.z; acc[0][3] += a.x * b.w;
                acc[1][0] += a.y * b.x; acc[1][1] += a.y * b.y; acc[1][2] += a.y * b.z; acc[1][3] += a.y * b.w;
                acc[2][0] += a.z * b.x; acc[2][1] += a.z * b.y; acc[2][2] += a.z * b.z; acc[2][3] += a.z * b.w;
                acc[3][0] += a.w * b.x; acc[3][1] += a.w * b.y; acc[3][2] += a.w * b.z; acc[3][3] += a.w * b.w;
            }
            if (more) {
                const int nb = cur ^ 1;
                As[nb][lq + 0][lrow] = av.x; As[nb][lq + 1][lrow] = av.y;
                As[nb][lq + 2][lrow] = av.z; As[nb][lq + 3][lrow] = av.w;
                Bs[nb][lq + 0][lrow] = bv.x; Bs[nb][lq + 1][lrow] = bv.y;
                Bs[nb][lq + 2][lrow] = bv.z; Bs[nb][lq + 3][lrow] = bv.w;
            }
            __syncthreads();
        }

        // ---- stage gates to smem so the elementwise thread sees its i/f/g/o ----
        #pragma unroll
        for (int i = 0; i < 4; ++i)
            #pragma unroll
            for (int j = 0; j < 4; ++j)
                Cs[ty + i][tx + j] = acc[i][j];
        __syncthreads();

        // ---- elementwise gates + state update ----
        #pragma unroll
        for (int q = 0; q < 4; ++q) {
            const int r = (tid >> 4) + q * 16;          // batch-local row
            const float iv = Cs[r][0 * HT + jj] + bias_i;
            const float fv = Cs[r][1 * HT + jj] + bias_f;
            const float gv = Cs[r][2 * HT + jj] + bias_g;
            const float ov = Cs[r][3 * HT + jj] + bias_o;
            const float ig = sigf(iv);
            const float fg = sigf(fv);
            const float gg = tanhf(gv);
            const float og = sigf(ov);
            const float c  = fg * c_reg[q] + ig * gg;
            c_reg[q] = c;
            const float h  = og * tanhf(c);
            const int b = m0 + r;
            hwr[b * HH + j0 + jj] = h;
            out[(long)b * (TT * HH) + (long)t * HH + j0 + jj] = h;
            if (t == TT - 1) {
                out[(long)BB * TT * HH + b * HH + j0 + jj] = h;
                out[(long)BB * TT * HH + (long)BB * HH + b * HH + j0 + jj] = c;
            }
        }

        grid_sync(base_gen + 2 + t);
    }
}

extern "C" void kernel_launch(void* const* d_in, const int* in_sizes, int n_in,
                              void* d_out, int out_size) {
    const float* x   = (const float*)d_in[0];
    const float* wih = (const float*)d_in[1];
    const float* whh = (const float*)d_in[2];
    const float* bih = (const float*)d_in[3];
    const float* bhh = (const float*)d_in[4];
    float* out = (float*)d_out;
    (void)in_sizes; (void)n_in; (void)out_size;
    lstm_persistent<<<NCTA, NTH>>>(x, wih, whh, bih, bhh, out);
}